// round 5
// baseline (speedup 1.0000x reference)
#include <cuda_runtime.h>

#define NG 8
#define NT 2048
#define NH 2048
#define NE 8
#define CAP 320

#define NTOK (NG * NT)                 // 16384
#define OFF_PMAX   (NTOK * NE)         // 131072
#define OFF_LOGITS (OFF_PMAX + NTOK)   // 147456

#define TPW 2                          // tokens per warp
#define THREADS 256                    // 8 warps -> 16 tokens per block
#define BLOCKS (NTOK / (TPW * 8))      // 1024
#define BPG (BLOCKS / NG)              // 128 blocks per group

typedef unsigned long long u64;

__device__ int g_expert_id[NTOK];
__device__ unsigned g_ctr[NG];         // monotone across graph replays

__device__ __forceinline__ u64 pack2(float a, float b) {
    u64 r;
    asm("mov.b64 %0, {%1, %2};" : "=l"(r) : "f"(a), "f"(b));
    return r;
}
__device__ __forceinline__ void unpack2(u64 v, float& a, float& b) {
    asm("mov.b64 {%0, %1}, %2;" : "=f"(a), "=f"(b) : "l"(v));
}
__device__ __forceinline__ void fma2(u64& d, u64 a, u64 b) {
    asm("fma.rn.f32x2 %0, %1, %2, %0;" : "+l"(d) : "l"(a), "l"(b));
}

extern __shared__ float4 sW[];         // [NE][NH/4] = 4096 float4 = 64KB

__global__ void __launch_bounds__(THREADS, 3)
router_fused_kernel(const float* __restrict__ hs,
                    const float* __restrict__ W,
                    const float* __restrict__ bias,
                    float* __restrict__ out) {
    const int tid   = threadIdx.x;
    const int lane  = tid & 31;
    const int gwarp = (blockIdx.x * THREADS + tid) >> 5;
    const int t0    = gwarp * TPW;

    const float4* __restrict__ xb = (const float4*)hs + (size_t)t0 * (NH / 4);

    // prefetch iteration 0's x BEFORE staging barrier (hides stage latency)
    float4 xc0 = __ldg(xb + lane);
    float4 xc1 = __ldg(xb + 512 + lane);

    // stage W into shared memory (once per block)
    {
        const float4* __restrict__ wv = (const float4*)W;
#pragma unroll
        for (int k = 0; k < (NE * NH / 4) / THREADS; ++k)   // 16
            sW[tid + k * THREADS] = __ldg(wv + tid + k * THREADS);
    }
    __syncthreads();

    // acc[tok][e], f32x2 packed along H (lo = even pair, hi = odd pair)
    u64 acc[TPW][NE];
#pragma unroll
    for (int tk = 0; tk < TPW; ++tk)
#pragma unroll
        for (int e = 0; e < NE; ++e) acc[tk][e] = 0ull;

#pragma unroll 2
    for (int it = 0; it < NH / (32 * 4); ++it) {            // 16 iterations
        // prefetch next iteration's x (software pipeline)
        float4 xn0, xn1;
        if (it < 15) {
            const int nidx = (it + 1) * 32 + lane;
            xn0 = __ldg(xb + nidx);
            xn1 = __ldg(xb + 512 + nidx);
        }
        const u64 x0lo = pack2(xc0.x, xc0.y), x0hi = pack2(xc0.z, xc0.w);
        const u64 x1lo = pack2(xc1.x, xc1.y), x1hi = pack2(xc1.z, xc1.w);
        const int idx = it * 32 + lane;
#pragma unroll
        for (int e = 0; e < NE; ++e) {
            float4 w = sW[e * (NH / 4) + idx];
            u64 wlo = pack2(w.x, w.y);
            u64 whi = pack2(w.z, w.w);
            fma2(acc[0][e], x0lo, wlo);
            fma2(acc[0][e], x0hi, whi);
            fma2(acc[1][e], x1lo, wlo);
            fma2(acc[1][e], x1hi, whi);
        }
        xc0 = xn0;
        xc1 = xn1;
    }

    // v[tk*8+e]: 16 partial sums per lane
    float v[16];
#pragma unroll
    for (int tk = 0; tk < TPW; ++tk)
#pragma unroll
        for (int e = 0; e < NE; ++e) {
            float a, b;
            unpack2(acc[tk][e], a, b);
            v[tk * 8 + e] = a + b;
        }

    // 4-step butterfly over lane bits {4,3,2,1}: lane L ends holding the
    // partial total of value index (L>>1)&15, summed over its bit0-parity
    // half; final xor-1 add completes the reduction (result duplicated).
#pragma unroll
    for (int s = 0; s < 4; ++s) {
        const int off  = 16 >> s;
        const int half = 8 >> s;
        const int sel  = (lane >> (4 - s)) & 1;
#pragma unroll
        for (int i = 0; i < half; ++i) {
            float a = v[i];
            float b = v[half + i];
            float mine = sel ? b : a;
            float send = sel ? a : b;
            float recv = __shfl_xor_sync(0xffffffffu, send, off);
            v[i] = mine + recv;
        }
    }
    v[0] += __shfl_xor_sync(0xffffffffu, v[0], 1);

    const int idx16 = (lane >> 1) & 15;        // value index
    const int e  = idx16 & 7;
    const int tk = idx16 >> 3;
    const int t  = t0 + tk;
    const float l = v[0] + __ldg(bias + e);

    // coalesced logits store: even lanes write 16 consecutive floats (64B)
    if ((lane & 1) == 0)
        out[OFF_LOGITS + (size_t)t0 * NE + idx16] = l;

    // max/argmax (first-max tie-break) + softmax denom within each token's
    // 8 experts: lanes sharing bits {0,4}, varying bits {1,2,3}
    float mx = l;
    int am = e;
#pragma unroll
    for (int off = 2; off <= 8; off <<= 1) {
        float omx = __shfl_xor_sync(0xffffffffu, mx, off);
        int   oam = __shfl_xor_sync(0xffffffffu, am, off);
        if (omx > mx || (omx == mx && oam < am)) { mx = omx; am = oam; }
    }
    float s = __expf(l - mx);
#pragma unroll
    for (int off = 2; off <= 8; off <<= 1)
        s += __shfl_xor_sync(0xffffffffu, s, off);

    if (lane == (tk << 4)) {                   // e==0 && bit0==0
        out[OFF_PMAX + t] = 1.0f / s;
        g_expert_id[t] = am;
    }

    // ----------------- fused capacity scan (last block of group) ------------
    __shared__ int s_g;
    __syncthreads();
    if (tid == 0) {
        __threadfence();                          // release our id writes
        const int grp = (int)(blockIdx.x / BPG);
        unsigned old = atomicAdd(&g_ctr[grp], 1u);
        s_g = (((old + 1u) & (BPG - 1u)) == 0u) ? grp : -1;
    }
    __syncthreads();
    const int g = s_g;
    if (g < 0) return;
    __threadfence();                              // acquire all id writes

    const int4* __restrict__ ids4 = (const int4*)(g_expert_id + g * NT);

    int myid[8];                                  // 2048 / 256 threads
    u64 c0 = 0ull, c1 = 0ull;
#pragma unroll
    for (int q = 0; q < 2; ++q) {
        int4 r = ids4[tid * 2 + q];
        myid[q * 4 + 0] = r.x; myid[q * 4 + 1] = r.y;
        myid[q * 4 + 2] = r.z; myid[q * 4 + 3] = r.w;
    }
#pragma unroll
    for (int i = 0; i < 8; ++i) {
        const int ee = myid[i];
        if (ee < 4) c0 += 1ull << (ee * 16);
        else        c1 += 1ull << ((ee - 4) * 16);
    }

    __shared__ u64 sA[THREADS], sB[THREADS];
    u64 i0 = c0, i1 = c1;
    sA[tid] = i0; sB[tid] = i1;
    __syncthreads();
#pragma unroll
    for (int off = 1; off < THREADS; off <<= 1) {
        u64 a = 0ull, b = 0ull;
        if (tid >= off) { a = sA[tid - off]; b = sB[tid - off]; }
        __syncthreads();
        i0 += a; i1 += b;
        sA[tid] = i0; sB[tid] = i1;
        __syncthreads();
    }
    u64 r0 = i0 - c0, r1 = i1 - c1;               // exclusive prefix

    __shared__ unsigned char sflag[NT];           // eid (3b) | keep (bit 3)
#pragma unroll
    for (int i = 0; i < 8; ++i) {
        const int ee = myid[i];
        int prio;
        if (ee < 4) { r0 += 1ull << (ee * 16);       prio = (int)((r0 >> (ee * 16)) & 0xFFFF); }
        else        { r1 += 1ull << ((ee - 4) * 16); prio = (int)((r1 >> ((ee - 4) * 16)) & 0xFFFF); }
        sflag[tid * 8 + i] = (unsigned char)(ee | ((prio <= CAP) ? 8 : 0));
    }
    __syncthreads();

    // coalesced one-hot write: 256 threads write consecutive float4
    float4* __restrict__ dst = (float4*)out + (size_t)g * NT * 2;
    for (int k = tid; k < NT * 2; k += THREADS) {
        const int fl   = sflag[k >> 1];
        const int ee   = fl & 7;
        const float kp = (fl & 8) ? 1.0f : 0.0f;
        const int rel  = ee - (k & 1) * 4;
        float4 v4 = make_float4(0.f, 0.f, 0.f, 0.f);
        if (rel >= 0 && rel < 4) (&v4.x)[rel] = kp;
        dst[k] = v4;
    }
}

extern "C" void kernel_launch(void* const* d_in, const int* in_sizes, int n_in,
                              void* d_out, int out_size) {
    const float* hs   = (const float*)d_in[0];
    const float* W    = (const float*)d_in[1];
    const float* bias = (const float*)d_in[2];
    float* out = (float*)d_out;

    static const int SMEM = NE * NH * (int)sizeof(float);   // 64KB dynamic
    cudaFuncSetAttribute(router_fused_kernel,
                         cudaFuncAttributeMaxDynamicSharedMemorySize, SMEM);
    router_fused_kernel<<<BLOCKS, THREADS, SMEM>>>(hs, W, bias, out);
}